// round 7
// baseline (speedup 1.0000x reference)
#include <cuda_runtime.h>
#include <cuda_bf16.h>
#include <cstdint>

// ---------------------------------------------------------------------------
// MeshRefineNet on GB300 (sm_103a), R7:
//   identity: agg_i = (sum_j act(x_j))@W1 + deg_i*b1
//   per layer: [gatherS kernel: S = sum of act(neighbor rows)]  (high occ)
//            + [persistent HMMA GEMM: out = [act(x)|S]@Wcat + b0 + deg*b1]
//   final: R4-style final_kernel (h0->out, h1s=h@W1+b1) + CSR gather3.
// Split-bf16 HMMA: Ahi@Bhi + Ahi@Blo + Alo@Bhi, fp32 accum (rel err ~1.5e-6).
// ---------------------------------------------------------------------------

#define NMAX 320000
#define EMAX 1000000

__device__ float g_bufA[NMAX * 128];
__device__ float g_bufB[NMAX * 128];
__device__ float g_S   [NMAX * 128];
__device__ float g_h1s [NMAX * 3];

// pre-split weight images: Bt[n][k], n in [0,128) outputs, k in [0,256)
// (k<128 -> W0[k][n], k>=128 -> W1[k-128][n]); hi/lo bf16, linear u32 pairs.
__device__ __align__(16) __nv_bfloat16 g_Whi[3][128 * 256];
__device__ __align__(16) __nv_bfloat16 g_Wlo[3][128 * 256];
__device__ float g_bias[3][256];           // [0:128) b0, [128:256) b1

// CSR scratch
__device__ int g_deg[NMAX];
__device__ int g_cur[NMAX];
__device__ int g_rowstart[NMAX + 1];
__device__ int g_adj[2 * EMAX];
__device__ int g_bsum[512];

// ======================= helpers ===========================================
__device__ __forceinline__ uint32_t smem_to_u32(const void* p) {
    uint32_t a;
    asm("{ .reg .u64 t; cvta.to.shared.u64 t, %1; cvt.u32.u64 %0, t; }"
        : "=r"(a) : "l"(p));
    return a;
}
__device__ __forceinline__ uint32_t pkbf(float a, float b) {
    __nv_bfloat162 t = __floats2bfloat162_rn(a, b);
    return *(uint32_t*)&t;
}
// XOR swizzle for 512B rows (256 halves = 32 16B-blocks per row)
__device__ __forceinline__ uint32_t aswz2(uint32_t row, uint32_t kb) {
    return (row << 9) + (((((kb) ^ row) & 7u) | (kb & 24u)) << 4);
}
__device__ __forceinline__ void ldsm_x4(uint32_t& r0, uint32_t& r1,
                                        uint32_t& r2, uint32_t& r3, uint32_t addr) {
    asm volatile("ldmatrix.sync.aligned.m8n8.x4.shared.b16 {%0,%1,%2,%3}, [%4];"
                 : "=r"(r0), "=r"(r1), "=r"(r2), "=r"(r3) : "r"(addr));
}
__device__ __forceinline__ void mma16816(float* d, const uint32_t* a,
                                         const uint32_t* b) {
    asm volatile("mma.sync.aligned.m16n8k16.row.col.f32.bf16.bf16.f32 "
                 "{%0,%1,%2,%3}, {%4,%5,%6,%7}, {%8,%9}, {%0,%1,%2,%3};"
                 : "+f"(d[0]), "+f"(d[1]), "+f"(d[2]), "+f"(d[3])
                 : "r"(a[0]), "r"(a[1]), "r"(a[2]), "r"(a[3]),
                   "r"(b[0]), "r"(b[1]));
}
__device__ __forceinline__ float4 relu4(float4 v) {
    v.x = fmaxf(v.x, 0.f); v.y = fmaxf(v.y, 0.f);
    v.z = fmaxf(v.z, 0.f); v.w = fmaxf(v.w, 0.f);
    return v;
}

// ======================= weight prep (once per launch) =====================
__global__ void prep_w_kernel(const float* __restrict__ W0, const float* __restrict__ b0,
                              const float* __restrict__ W1, const float* __restrict__ b1,
                              __nv_bfloat16* __restrict__ hi, __nv_bfloat16* __restrict__ lo,
                              float* __restrict__ biasOut)
{
    int t0 = blockIdx.x * blockDim.x + threadIdx.x;
    if (t0 < 128) { biasOut[t0] = b0[t0]; biasOut[128 + t0] = b1[t0]; }
    uint32_t* hip = (uint32_t*)hi;
    uint32_t* lop = (uint32_t*)lo;
    for (int idx = t0; idx < 128 * 128; idx += blockDim.x * gridDim.x) {
        int n = idx >> 7, p = idx & 127;       // p = u32 pair index, k = 2p
        int k = p * 2;
        float x0 = (k < 128)     ? W0[k * 128 + n]       : W1[(k - 128) * 128 + n];
        float x1 = (k + 1 < 128) ? W0[(k + 1) * 128 + n] : W1[(k + 1 - 128) * 128 + n];
        float h0f = __bfloat162float(__float2bfloat16_rn(x0));
        float h1f = __bfloat162float(__float2bfloat16_rn(x1));
        hip[idx] = pkbf(x0, x1);
        lop[idx] = pkbf(x0 - h0f, x1 - h1f);
    }
}

// ======================= CSR build =========================================
__global__ void zero_deg_kernel(int* deg, int n) {
    int i = blockIdx.x * blockDim.x + threadIdx.x;
    if (i < n) deg[i] = 0;
}
__global__ void count_deg_kernel(const int2* __restrict__ edges, int* deg, int E) {
    int e = blockIdx.x * blockDim.x + threadIdx.x;
    if (e >= E) return;
    int2 ed = __ldg(&edges[e]);
    atomicAdd(&deg[ed.x], 1);
    atomicAdd(&deg[ed.y], 1);
}
__global__ __launch_bounds__(1024)
void scanA_kernel(const int* __restrict__ deg, int* rowstart, int* bsum, int n) {
    __shared__ int s[1024];
    int t = threadIdx.x;
    int i = blockIdx.x * 1024 + t;
    int v = (i < n) ? deg[i] : 0;
    s[t] = v;
    __syncthreads();
#pragma unroll
    for (int o = 1; o < 1024; o <<= 1) {
        int x = (t >= o) ? s[t - o] : 0;
        __syncthreads();
        s[t] += x;
        __syncthreads();
    }
    if (i < n) rowstart[i] = s[t] - v;
    if (t == 1023) bsum[blockIdx.x] = s[1023];
}
__global__ __launch_bounds__(512)
void scanB_kernel(int* bsum, int nb) {
    __shared__ int s[512];
    int t = threadIdx.x;
    int v = (t < nb) ? bsum[t] : 0;
    s[t] = v;
    __syncthreads();
#pragma unroll
    for (int o = 1; o < 512; o <<= 1) {
        int x = (t >= o) ? s[t - o] : 0;
        __syncthreads();
        s[t] += x;
        __syncthreads();
    }
    if (t < nb) bsum[t] = s[t] - v;
}
__global__ __launch_bounds__(1024)
void scanC_kernel(int* rowstart, int* cur, const int* __restrict__ bsum,
                  int n, int total) {
    int i = blockIdx.x * 1024 + threadIdx.x;
    if (i < n) {
        int r = rowstart[i] + bsum[blockIdx.x];
        rowstart[i] = r;
        cur[i] = r;
    }
    if (i == 0) rowstart[n] = total;
}
__global__ void fill_adj_kernel(const int2* __restrict__ edges, int* cur,
                                int* adj, int E) {
    int e = blockIdx.x * blockDim.x + threadIdx.x;
    if (e >= E) return;
    int2 ed = __ldg(&edges[e]);
    int ps = atomicAdd(&cur[ed.x], 1);
    adj[ps] = ed.y;
    int pd = atomicAdd(&cur[ed.y], 1);
    adj[pd] = ed.x;
}

// ======================= gatherS: S_i = sum_j act(x_j) =====================
// Warp per node, high occupancy; lane covers 4 contiguous floats.
template<int ACT>   // 0 = identity, 1 = relu
__global__ __launch_bounds__(256)
void gatherS_kernel(const int* __restrict__ rowstart, const int* __restrict__ adj,
                    const float* __restrict__ in, float* __restrict__ S, int n)
{
    int node = blockIdx.x * 8 + (threadIdx.x >> 5);
    int lane = threadIdx.x & 31;
    if (node >= n) return;
    int rs = __ldg(&rowstart[node]);
    int re = __ldg(&rowstart[node + 1]);
    int k0 = lane * 4;
    float4 acc = make_float4(0.f, 0.f, 0.f, 0.f);
    int e = rs;
    for (; e + 3 < re; e += 4) {
        int j0 = __ldg(&adj[e]),     j1 = __ldg(&adj[e + 1]);
        int j2 = __ldg(&adj[e + 2]), j3 = __ldg(&adj[e + 3]);
        float4 v0 = __ldg((const float4*)(in + (size_t)j0 * 128 + k0));
        float4 v1 = __ldg((const float4*)(in + (size_t)j1 * 128 + k0));
        float4 v2 = __ldg((const float4*)(in + (size_t)j2 * 128 + k0));
        float4 v3 = __ldg((const float4*)(in + (size_t)j3 * 128 + k0));
        if (ACT) { v0 = relu4(v0); v1 = relu4(v1); v2 = relu4(v2); v3 = relu4(v3); }
        acc.x += v0.x + v1.x + v2.x + v3.x;
        acc.y += v0.y + v1.y + v2.y + v3.y;
        acc.z += v0.z + v1.z + v2.z + v3.z;
        acc.w += v0.w + v1.w + v2.w + v3.w;
    }
    for (; e < re; e++) {
        int j = __ldg(&adj[e]);
        float4 v = __ldg((const float4*)(in + (size_t)j * 128 + k0));
        if (ACT) v = relu4(v);
        acc.x += v.x; acc.y += v.y; acc.z += v.z; acc.w += v.w;
    }
    *(float4*)(S + (size_t)node * 128 + k0) = acc;
}

// ======================= persistent HMMA GEMM (K=256 -> N=128) =============
// smem: B_hi 64K | B_lo 64K | A dbuf 2 x (hi 16K + lo 16K) = 192 KB total.
static constexpr int SM_B_HI = 0;
static constexpr int SM_B_LO = 65536;
static constexpr int SM_A    = 131072;
static constexpr int A_STRIDE = 32768;     // per buffer
static constexpr int A_LO     = 16384;     // lo offset within buffer
static constexpr int SM_DYN  = 196608;

// IN_RELU: relu on own row x (S is already activated by gatherS)
template<int IN_RELU>
__global__ __launch_bounds__(512, 1)
void gemm_k256_kernel(const float* __restrict__ in,
                      const float* __restrict__ S,
                      const __nv_bfloat16* __restrict__ Whi,
                      const __nv_bfloat16* __restrict__ Wlo,
                      const float* __restrict__ bias256,
                      const int* __restrict__ deg,
                      float* __restrict__ out,
                      int n, int numTiles)
{
    extern __shared__ char sm[];
    const uint32_t sbase = smem_to_u32(sm);
    const int tid  = threadIdx.x;
    const int wid  = tid >> 5;
    const int lane = tid & 31;

    // ---- stage B hi/lo once (swizzled 512B rows) ----
    {
        const uint32_t* srcH = (const uint32_t*)Whi;
        const uint32_t* srcL = (const uint32_t*)Wlo;
#pragma unroll
        for (int u = 0; u < 32; u++) {
            int idx = u * 512 + tid;            // 0..16383
            int row = idx >> 7, p = idx & 127;
            uint32_t off = aswz2(row, p >> 2) + (p & 3) * 4;
            *(uint32_t*)(sm + SM_B_HI + off) = srcH[idx];
            *(uint32_t*)(sm + SM_B_LO + off) = srcL[idx];
        }
    }

    int tile = blockIdx.x;
    if (tile >= numTiles) { __syncthreads(); return; }

    // MMA geometry: warp grid 2(m) x 8(n), warp tile 16x16
    const int mbase = (wid & 1) * 16;
    const int nbase = (wid >> 1) * 16;
    const int aRow  = lane & 15;
    const int aKs   = lane >> 4;
    const int bTile = lane >> 3;
    const int bRow  = (lane & 7) + ((bTile >> 1) << 3);
    const int bKs   = bTile & 1;

    // ---- stage tile0 into buf 0: A = [x | S], 32 rows x 256 halves --------
    {
        const int tb = tile * 32;
        char* ab = sm + SM_A;
#pragma unroll
        for (int u = 0; u < 8; u++) {
            int idx = u * 512 + tid;           // 0..4095 u32-pair slots
            int row = idx >> 7, p = idx & 127; // p = u32 idx (k pair), k=2p
            int gr = tb + row;
            float2 xv = make_float2(0.f, 0.f);
            if (gr < n) {
                if (p < 64) {
                    xv = *(const float2*)(in + (size_t)gr * 128 + p * 2);
                    if (IN_RELU) { xv.x = fmaxf(xv.x, 0.f); xv.y = fmaxf(xv.y, 0.f); }
                } else {
                    xv = *(const float2*)(S + (size_t)gr * 128 + (p - 64) * 2);
                }
            }
            float hx = __bfloat162float(__float2bfloat16_rn(xv.x));
            float hy = __bfloat162float(__float2bfloat16_rn(xv.y));
            uint32_t off = aswz2(row, p >> 2) + (p & 3) * 4;
            *(uint32_t*)(ab + off)        = pkbf(xv.x, xv.y);
            *(uint32_t*)(ab + A_LO + off) = pkbf(xv.x - hx, xv.y - hy);
        }
    }
    __syncthreads();

    int buf = 0;
    for (;;) {
        const int tb = tile * 32;
        const int next = tile + gridDim.x;
        const bool hasNext = next < numTiles;

        // ---- prefetch next tile into registers (pure strided LDG) ---------
        float2 xr[8];
        if (hasNext) {
            const int tb2 = next * 32;
#pragma unroll
            for (int u = 0; u < 8; u++) {
                int idx = u * 512 + tid;
                int row = idx >> 7, p = idx & 127;
                int gr = tb2 + row;
                float2 xv = make_float2(0.f, 0.f);
                if (gr < n) {
                    if (p < 64)
                        xv = *(const float2*)(in + (size_t)gr * 128 + p * 2);
                    else
                        xv = *(const float2*)(S + (size_t)gr * 128 + (p - 64) * 2);
                }
                xr[u] = xv;
            }
        }

        // ---- MMA on current buffer (K=256, 3 splits) ----------------------
        float d[2][4];
#pragma unroll
        for (int nh = 0; nh < 2; nh++)
#pragma unroll
            for (int q = 0; q < 4; q++) d[nh][q] = 0.f;

        const uint32_t abufB = sbase + SM_A + buf * A_STRIDE;
#pragma unroll
        for (int s = 0; s < 3; s++) {
            const uint32_t aB = abufB + ((s == 2) ? A_LO : 0);
            const uint32_t bB = sbase + ((s == 1) ? SM_B_LO : SM_B_HI);
#pragma unroll
            for (int kk = 0; kk < 16; kk++) {
                const int kb0 = kk * 2;
                uint32_t a[4];
                ldsm_x4(a[0], a[1], a[2], a[3], aB + aswz2(mbase + aRow, kb0 + aKs));
                uint32_t b0, b1, b2, b3;
                ldsm_x4(b0, b1, b2, b3, bB + aswz2(nbase + bRow, kb0 + bKs));
                uint32_t blo[2] = {b0, b1};
                uint32_t bhi[2] = {b2, b3};
                mma16816(d[0], a, blo);
                mma16816(d[1], a, bhi);
            }
        }

        // ---- epilogue: out = v + b0 + deg*b1 -------------------------------
        {
            int r0 = tb + mbase + (lane >> 2);
            int colBase = nbase + 2 * (lane & 3);
#pragma unroll
            for (int h = 0; h < 2; h++) {
                int row = r0 + h * 8;
                if (row >= n) continue;
                float dg = (float)__ldg(&deg[row]);
#pragma unroll
                for (int nh = 0; nh < 2; nh++) {
                    int col = colBase + nh * 8;
                    float2 b0v = __ldg((const float2*)(bias256 + col));
                    float2 b1v = __ldg((const float2*)(bias256 + 128 + col));
                    float2 v;
                    v.x = d[nh][2 * h + 0] + b0v.x + dg * b1v.x;
                    v.y = d[nh][2 * h + 1] + b0v.y + dg * b1v.y;
                    *(float2*)(out + (size_t)row * 128 + col) = v;
                }
            }
        }

        if (!hasNext) break;

        // ---- convert + store prefetched tile into other buffer ------------
        {
            char* ab = sm + SM_A + (buf ^ 1) * A_STRIDE;
#pragma unroll
            for (int u = 0; u < 8; u++) {
                int idx = u * 512 + tid;
                int row = idx >> 7, p = idx & 127;
                float2 xv = xr[u];
                if (IN_RELU && p < 64) {
                    xv.x = fmaxf(xv.x, 0.f); xv.y = fmaxf(xv.y, 0.f);
                }
                float hx = __bfloat162float(__float2bfloat16_rn(xv.x));
                float hy = __bfloat162float(__float2bfloat16_rn(xv.y));
                uint32_t off = aswz2(row, p >> 2) + (p & 3) * 4;
                *(uint32_t*)(ab + off)        = pkbf(xv.x, xv.y);
                *(uint32_t*)(ab + A_LO + off) = pkbf(xv.x - hx, xv.y - hy);
            }
        }
        __syncthreads();
        tile = next;
        buf ^= 1;
    }
}

// ======================= final layer (dout=3), R4-proven ====================
__global__ __launch_bounds__(256)
void final_kernel(const float* __restrict__ in, const float* __restrict__ feat,
                  const float* __restrict__ W0, const float* __restrict__ b0,
                  const float* __restrict__ W1, const float* __restrict__ b1,
                  float* __restrict__ out, float* __restrict__ h1s, int n)
{
    __shared__ float ws[128][6];
    __shared__ float bs[6];
    int tid = threadIdx.x;
    for (int idx = tid; idx < 768; idx += 256) {
        int k = idx / 6, j = idx % 6;
        ws[k][j] = (j < 3) ? __ldg(&W0[k * 3 + j]) : __ldg(&W1[k * 3 + (j - 3)]);
    }
    if (tid < 3)      bs[tid] = __ldg(&b0[tid]);
    else if (tid < 6) bs[tid] = __ldg(&b1[tid - 3]);
    __syncthreads();

    int lane = tid & 31;
    int node = blockIdx.x * 8 + (tid >> 5);
    if (node >= n) return;

    float acc[6] = {0.f, 0.f, 0.f, 0.f, 0.f, 0.f};
    const float* xin = in   + (size_t)node * 128;
    const float* xf  = feat + (size_t)node * 128;
#pragma unroll
    for (int f = 0; f < 4; f++) {
        int k = f * 32 + lane;
        float x = fmaxf(xin[k], 0.f) + xf[k];
#pragma unroll
        for (int j = 0; j < 6; j++) acc[j] += x * ws[k][j];
    }
#pragma unroll
    for (int j = 0; j < 6; j++) {
#pragma unroll
        for (int o = 16; o > 0; o >>= 1)
            acc[j] += __shfl_xor_sync(0xffffffffu, acc[j], o);
    }
    if (lane == 0) {
        out[node * 3 + 0] = acc[0] + bs[0];
        out[node * 3 + 1] = acc[1] + bs[1];
        out[node * 3 + 2] = acc[2] + bs[2];
        h1s[node * 3 + 0] = acc[3] + bs[3];
        h1s[node * 3 + 1] = acc[4] + bs[4];
        h1s[node * 3 + 2] = acc[5] + bs[5];
    }
}

// final gather (3-wide), CSR non-atomic: out[i] += sum_j h1s[j]
__global__ void gather3_kernel(const int* __restrict__ rowstart,
                               const int* __restrict__ adj,
                               const float* __restrict__ h1s,
                               float* __restrict__ out, int n)
{
    int i = blockIdx.x * blockDim.x + threadIdx.x;
    if (i >= n) return;
    int rs = __ldg(&rowstart[i]);
    int re = __ldg(&rowstart[i + 1]);
    float a0 = 0.f, a1 = 0.f, a2 = 0.f;
    for (int e = rs; e < re; e++) {
        int j = __ldg(&adj[e]);
        a0 += __ldg(&h1s[j * 3 + 0]);
        a1 += __ldg(&h1s[j * 3 + 1]);
        a2 += __ldg(&h1s[j * 3 + 2]);
    }
    out[i * 3 + 0] += a0;
    out[i * 3 + 1] += a1;
    out[i * 3 + 2] += a2;
}

// ======================= launch ============================================
extern "C" void kernel_launch(void* const* d_in, const int* in_sizes, int n_in,
                              void* d_out, int out_size)
{
    const float* feat  = (const float*)d_in[0];
    const int2*  edges = (const int2*) d_in[1];
    const int N = in_sizes[0] / 128;
    const int E = in_sizes[1] / 2;

    const float *W0[4], *B0[4], *W1[4], *B1[4];
    for (int i = 0; i < 4; i++) {
        W0[i] = (const float*)d_in[2 + 4 * i];
        B0[i] = (const float*)d_in[3 + 4 * i];
        W1[i] = (const float*)d_in[4 + 4 * i];
        B1[i] = (const float*)d_in[5 + 4 * i];
    }

    float *bufA, *bufB, *Sbuf, *h1s, *biasAll;
    __nv_bfloat16 *whiAll, *wloAll;
    int *deg, *cur, *rowstart, *adj, *bsum;
    cudaGetSymbolAddress((void**)&bufA, g_bufA);
    cudaGetSymbolAddress((void**)&bufB, g_bufB);
    cudaGetSymbolAddress((void**)&Sbuf, g_S);
    cudaGetSymbolAddress((void**)&h1s,  g_h1s);
    cudaGetSymbolAddress((void**)&whiAll, g_Whi);
    cudaGetSymbolAddress((void**)&wloAll, g_Wlo);
    cudaGetSymbolAddress((void**)&biasAll, g_bias);
    cudaGetSymbolAddress((void**)&deg, g_deg);
    cudaGetSymbolAddress((void**)&cur, g_cur);
    cudaGetSymbolAddress((void**)&rowstart, g_rowstart);
    cudaGetSymbolAddress((void**)&adj, g_adj);
    cudaGetSymbolAddress((void**)&bsum, g_bsum);

    cudaFuncSetAttribute(gemm_k256_kernel<0>, cudaFuncAttributeMaxDynamicSharedMemorySize, SM_DYN);
    cudaFuncSetAttribute(gemm_k256_kernel<1>, cudaFuncAttributeMaxDynamicSharedMemorySize, SM_DYN);

    // weight prep (K=256 concat images)
    for (int l = 0; l < 3; l++) {
        prep_w_kernel<<<16, 256>>>(W0[l], B0[l], W1[l], B1[l],
                                   whiAll + l * 128 * 256, wloAll + l * 128 * 256,
                                   biasAll + l * 256);
    }

    // CSR build
    const int NB = (N + 1023) / 1024;
    zero_deg_kernel<<<(N + 255) / 256, 256>>>(deg, N);
    count_deg_kernel<<<(E + 255) / 256, 256>>>(edges, deg, E);
    scanA_kernel<<<NB, 1024>>>(deg, rowstart, bsum, N);
    scanB_kernel<<<1, 512>>>(bsum, NB);
    scanC_kernel<<<NB, 1024>>>(rowstart, cur, bsum, N, 2 * E);
    fill_adj_kernel<<<(E + 255) / 256, 256>>>(edges, cur, adj, E);

    const int numTiles = (N + 31) / 32;
    const int PGRID = 148;
    const int gaBlocks = (N + 7) / 8;
    float* out = (float*)d_out;

    // layer 0 (identity act)
    gatherS_kernel<0><<<gaBlocks, 256>>>(rowstart, adj, feat, Sbuf, N);
    gemm_k256_kernel<0><<<PGRID, 512, SM_DYN>>>(feat, Sbuf,
        whiAll, wloAll, biasAll, deg, bufA, N, numTiles);
    // layer 1 (relu act)
    gatherS_kernel<1><<<gaBlocks, 256>>>(rowstart, adj, bufA, Sbuf, N);
    gemm_k256_kernel<1><<<PGRID, 512, SM_DYN>>>(bufA, Sbuf,
        whiAll + 128 * 256, wloAll + 128 * 256, biasAll + 256, deg, bufB, N, numTiles);
    // layer 2 (relu act)
    gatherS_kernel<1><<<gaBlocks, 256>>>(rowstart, adj, bufB, Sbuf, N);
    gemm_k256_kernel<1><<<PGRID, 512, SM_DYN>>>(bufB, Sbuf,
        whiAll + 2 * 128 * 256, wloAll + 2 * 128 * 256, biasAll + 2 * 256, deg, bufA, N, numTiles);
    // final: x = relu(bufA)+feat inside final_kernel; h1s = x@W1+b1
    final_kernel<<<gaBlocks, 256>>>(bufA, feat, W0[3], B0[3], W1[3], B1[3], out, h1s, N);
    gather3_kernel<<<(N + 255) / 256, 256>>>(rowstart, adj, h1s, out, N);
}

// round 8
// speedup vs baseline: 2.4008x; 2.4008x over previous
#include <cuda_runtime.h>
#include <cuda_fp16.h>
#include <cstdint>

// ---------------------------------------------------------------------------
// MeshRefineNet on GB300 (sm_103a), R8 = R4 structure (proven 1615us) with
// the GEMM converted from 3-split bf16 (3x MMA work) to SINGLE-PASS fp16.
//   layer i: h0 = x@W0+b0; h1 = x@W1+b1; out = h0 + sum_{j in N(i)} h1[j]
//   relu after layers 0..2; skip before layer 3; layer 3 dout=3.
// fp16 inputs (11 mantissa bits), fp32 accum -> est rel err ~1e-4 (thr 1e-3).
// ---------------------------------------------------------------------------

#define NMAX 320000
#define EMAX 1000000

__device__ float g_bufA[NMAX * 128];
__device__ float g_bufB[NMAX * 128];
__device__ float g_h1 [NMAX * 128];
__device__ float g_h1s[NMAX * 3];

// fp16 weight images: Bt[n][k] = W[k][n] (n<128 from W0, else W1), linear.
__device__ __align__(16) __half g_W16[3][256 * 128];
__device__ float g_bias[3][256];

// CSR scratch
__device__ int g_deg[NMAX];
__device__ int g_cur[NMAX];
__device__ int g_rowstart[NMAX + 1];
__device__ int g_adj[2 * EMAX];
__device__ int g_bsum[512];

// ======================= helpers ===========================================
__device__ __forceinline__ uint32_t smem_to_u32(const void* p) {
    uint32_t a;
    asm("{ .reg .u64 t; cvta.to.shared.u64 t, %1; cvt.u32.u64 %0, t; }"
        : "=r"(a) : "l"(p));
    return a;
}
__device__ __forceinline__ uint32_t pkh(float a, float b) {
    __half2 t = __floats2half2_rn(a, b);
    return *(uint32_t*)&t;
}
// XOR-swizzled offset for 16-bit tile images with 256B rows (128 halves/row).
__device__ __forceinline__ uint32_t aswz(uint32_t row, uint32_t kblk) {
    return row * 256u + ((((kblk ^ row) & 7u) | (kblk & 8u)) << 4);
}
__device__ __forceinline__ void ldsm_x4(uint32_t& r0, uint32_t& r1,
                                        uint32_t& r2, uint32_t& r3, uint32_t addr) {
    asm volatile("ldmatrix.sync.aligned.m8n8.x4.shared.b16 {%0,%1,%2,%3}, [%4];"
                 : "=r"(r0), "=r"(r1), "=r"(r2), "=r"(r3) : "r"(addr));
}
__device__ __forceinline__ void mma16816(float* d, const uint32_t* a,
                                         const uint32_t* b) {
    asm volatile("mma.sync.aligned.m16n8k16.row.col.f32.f16.f16.f32 "
                 "{%0,%1,%2,%3}, {%4,%5,%6,%7}, {%8,%9}, {%0,%1,%2,%3};"
                 : "+f"(d[0]), "+f"(d[1]), "+f"(d[2]), "+f"(d[3])
                 : "r"(a[0]), "r"(a[1]), "r"(a[2]), "r"(a[3]),
                   "r"(b[0]), "r"(b[1]));
}

// ======================= weight prep (once per launch) =====================
__global__ void prep_w_kernel(const float* __restrict__ W0, const float* __restrict__ b0,
                              const float* __restrict__ W1, const float* __restrict__ b1,
                              __half* __restrict__ w16, float* __restrict__ biasOut)
{
    int t0 = blockIdx.x * blockDim.x + threadIdx.x;
    if (t0 < 256) biasOut[t0] = (t0 < 128) ? b0[t0] : b1[t0 - 128];
    uint32_t* wp = (uint32_t*)w16;
    for (int idx = t0; idx < 256 * 64; idx += blockDim.x * gridDim.x) {
        int n = idx >> 6, p = idx & 63;
        int k = p * 2;
        float x0, x1;
        if (n < 128) { x0 = W0[k * 128 + n]; x1 = W0[(k + 1) * 128 + n]; }
        else         { x0 = W1[k * 128 + n - 128]; x1 = W1[(k + 1) * 128 + n - 128]; }
        wp[idx] = pkh(x0, x1);
    }
}

// ======================= CSR build =========================================
__global__ void zero_deg_kernel(int* deg, int n) {
    int i = blockIdx.x * blockDim.x + threadIdx.x;
    if (i < n) deg[i] = 0;
}
__global__ void count_deg_kernel(const int2* __restrict__ edges, int* deg, int E) {
    int e = blockIdx.x * blockDim.x + threadIdx.x;
    if (e >= E) return;
    int2 ed = __ldg(&edges[e]);
    atomicAdd(&deg[ed.x], 1);
    atomicAdd(&deg[ed.y], 1);
}
__global__ __launch_bounds__(1024)
void scanA_kernel(const int* __restrict__ deg, int* rowstart, int* bsum, int n) {
    __shared__ int s[1024];
    int t = threadIdx.x;
    int i = blockIdx.x * 1024 + t;
    int v = (i < n) ? deg[i] : 0;
    s[t] = v;
    __syncthreads();
#pragma unroll
    for (int o = 1; o < 1024; o <<= 1) {
        int x = (t >= o) ? s[t - o] : 0;
        __syncthreads();
        s[t] += x;
        __syncthreads();
    }
    if (i < n) rowstart[i] = s[t] - v;
    if (t == 1023) bsum[blockIdx.x] = s[1023];
}
__global__ __launch_bounds__(512)
void scanB_kernel(int* bsum, int nb) {
    __shared__ int s[512];
    int t = threadIdx.x;
    int v = (t < nb) ? bsum[t] : 0;
    s[t] = v;
    __syncthreads();
#pragma unroll
    for (int o = 1; o < 512; o <<= 1) {
        int x = (t >= o) ? s[t - o] : 0;
        __syncthreads();
        s[t] += x;
        __syncthreads();
    }
    if (t < nb) bsum[t] = s[t] - v;
}
__global__ __launch_bounds__(1024)
void scanC_kernel(int* rowstart, int* cur, const int* __restrict__ bsum,
                  int n, int total) {
    int i = blockIdx.x * 1024 + threadIdx.x;
    if (i < n) {
        int r = rowstart[i] + bsum[blockIdx.x];
        rowstart[i] = r;
        cur[i] = r;
    }
    if (i == 0) rowstart[n] = total;
}
__global__ void fill_adj_kernel(const int2* __restrict__ edges, int* cur,
                                int* adj, int E) {
    int e = blockIdx.x * blockDim.x + threadIdx.x;
    if (e >= E) return;
    int2 ed = __ldg(&edges[e]);
    int ps = atomicAdd(&cur[ed.x], 1);
    adj[ps] = ed.y;
    int pd = atomicAdd(&cur[ed.y], 1);
    adj[pd] = ed.x;
}

// ======================= persistent fp16 HMMA dual-GEMM ====================
// smem: B 64K | A dbuf 2 x 16K = 96 KB.
static constexpr int SM_B    = 0;
static constexpr int SM_A    = 65536;
static constexpr int A_STRIDE = 16384;
static constexpr int SM_DYN  = 98304;

template<int MODE>   // 0 = raw input, 1 = relu(input)
__global__ __launch_bounds__(512, 1)
void gemm_persist_kernel(const float* __restrict__ in,
                         const __half* __restrict__ W16,
                         const float* __restrict__ bias256,
                         float* __restrict__ agg, float* __restrict__ h1v,
                         int n, int numTiles)
{
    extern __shared__ char sm[];
    const uint32_t sbase = smem_to_u32(sm);
    const int tid  = threadIdx.x;
    const int wid  = tid >> 5;
    const int lane = tid & 31;

    // ---- stage B once (swizzled 256B rows) ----
    {
        const uint32_t* src = (const uint32_t*)W16;
#pragma unroll
        for (int u = 0; u < 32; u++) {
            int idx = u * 512 + tid;            // 0..16383
            int row = idx >> 6, p = idx & 63;
            uint32_t off = aswz(row, p >> 2) + (p & 3) * 4;
            *(uint32_t*)(sm + SM_B + off) = src[idx];
        }
    }

    int tile = blockIdx.x;
    if (tile >= numTiles) { __syncthreads(); return; }

    // ---- stage A tile0 into buf0 ----
    {
        int tb = tile * 64;
#pragma unroll
        for (int u = 0; u < 8; u++) {
            int idx = u * 512 + tid;           // 0..4095
            int row = idx >> 6, p = idx & 63;
            int gr = tb + row;
            float2 xv = make_float2(0.f, 0.f);
            if (gr < n) xv = *(const float2*)(in + (size_t)gr * 128 + p * 2);
            if (MODE == 1) { xv.x = fmaxf(xv.x, 0.f); xv.y = fmaxf(xv.y, 0.f); }
            uint32_t off = aswz(row, p >> 2) + (p & 3) * 4;
            *(uint32_t*)(sm + SM_A + off) = pkh(xv.x, xv.y);
        }
    }
    __syncthreads();

    // warp grid: 2(m) x 8(n); warp tile 32x32
    const int mbase = (wid & 1) * 32;
    const int nbase = (wid >> 1) * 32;
    const int aRow  = lane & 15;
    const int aKs   = lane >> 4;
    const int bTile = lane >> 3;
    const int bRow  = (lane & 7) + ((bTile >> 1) << 3);
    const int colq  = 2 * (lane & 3);

    for (int it = 0; ; it++) {
        const int buf = it & 1;
        const int tb = tile * 64;
        const int next = tile + gridDim.x;
        const bool hasNext = next < numTiles;

        // prefetch next A tile (LDG under compute)
        float2 pf[8];
        if (hasNext) {
            int ntb = next * 64;
#pragma unroll
            for (int u = 0; u < 8; u++) {
                int idx = u * 512 + tid;
                int row = idx >> 6, p = idx & 63;
                int gr = ntb + row;
                pf[u] = (gr < n) ? *(const float2*)(in + (size_t)gr * 128 + p * 2)
                                 : make_float2(0.f, 0.f);
            }
        }

        // ---- compute: single fp16 pass, K=128 (8 k-steps) ----
        float d[2][4][4];
#pragma unroll
        for (int mb = 0; mb < 2; mb++)
#pragma unroll
            for (int nb = 0; nb < 4; nb++)
#pragma unroll
                for (int q = 0; q < 4; q++) d[mb][nb][q] = 0.f;

        const uint32_t aB = sbase + SM_A + buf * A_STRIDE;
        const uint32_t bB = sbase + SM_B;
#pragma unroll
        for (int kk = 0; kk < 8; kk++) {
            const int kblk0 = kk * 2;
            uint32_t a[2][4];
#pragma unroll
            for (int mb = 0; mb < 2; mb++) {
                uint32_t addr = aB + aswz(mbase + mb * 16 + aRow, kblk0 + aKs);
                ldsm_x4(a[mb][0], a[mb][1], a[mb][2], a[mb][3], addr);
            }
#pragma unroll
            for (int nb2 = 0; nb2 < 2; nb2++) {
                uint32_t addr = bB + aswz(nbase + nb2 * 16 + bRow,
                                          kblk0 + (bTile & 1));
                uint32_t b0, b1, b2, b3;
                ldsm_x4(b0, b1, b2, b3, addr);
                uint32_t blo[2] = {b0, b1};
                uint32_t bhi[2] = {b2, b3};
                mma16816(d[0][nb2 * 2 + 0], a[0], blo);
                mma16816(d[1][nb2 * 2 + 0], a[1], blo);
                mma16816(d[0][nb2 * 2 + 1], a[0], bhi);
                mma16816(d[1][nb2 * 2 + 1], a[1], bhi);
            }
        }

        // ---- epilogue: +bias, cols<128 -> agg(h0), else h1 ----
#pragma unroll
        for (int mb = 0; mb < 2; mb++) {
#pragma unroll
            for (int h = 0; h < 2; h++) {
                int row = tb + mbase + mb * 16 + (lane >> 2) + h * 8;
                if (row >= n) continue;
#pragma unroll
                for (int nb = 0; nb < 4; nb++) {
                    int col = nbase + nb * 8 + colq;
                    float2 bv = __ldg((const float2*)(bias256 + col));
                    float2 v;
                    v.x = d[mb][nb][2 * h + 0] + bv.x;
                    v.y = d[mb][nb][2 * h + 1] + bv.y;
                    if (col < 128)
                        *(float2*)(agg + (size_t)row * 128 + col) = v;
                    else
                        *(float2*)(h1v + (size_t)row * 128 + (col - 128)) = v;
                }
            }
        }

        if (!hasNext) break;

        // ---- convert + store prefetched tile into other buffer ----
        {
            char* ab = sm + SM_A + (buf ^ 1) * A_STRIDE;
#pragma unroll
            for (int u = 0; u < 8; u++) {
                int idx = u * 512 + tid;
                int row = idx >> 6, p = idx & 63;
                float2 xv = pf[u];
                if (MODE == 1) { xv.x = fmaxf(xv.x, 0.f); xv.y = fmaxf(xv.y, 0.f); }
                uint32_t off = aswz(row, p >> 2) + (p & 3) * 4;
                *(uint32_t*)(ab + off) = pkh(xv.x, xv.y);
            }
        }
        tile = next;
        __syncthreads();
    }
}

// ======================= CSR gather (128-wide), R4-proven ==================
__global__ __launch_bounds__(256)
void gather128_kernel(const int* __restrict__ rowstart, const int* __restrict__ adj,
                      const float* __restrict__ h1, float* __restrict__ agg, int n)
{
    int node = blockIdx.x * 8 + (threadIdx.x >> 5);
    int lane = threadIdx.x & 31;
    if (node >= n) return;
    int rs = __ldg(&rowstart[node]);
    int re = __ldg(&rowstart[node + 1]);
    float* ap = agg + (size_t)node * 128 + lane * 4;
    float4 acc = *(float4*)ap;
    int e = rs;
    for (; e + 1 < re; e += 2) {
        int j0 = __ldg(&adj[e]);
        int j1 = __ldg(&adj[e + 1]);
        float4 v0 = __ldg((const float4*)(h1 + (size_t)j0 * 128 + lane * 4));
        float4 v1 = __ldg((const float4*)(h1 + (size_t)j1 * 128 + lane * 4));
        acc.x += v0.x + v1.x; acc.y += v0.y + v1.y;
        acc.z += v0.z + v1.z; acc.w += v0.w + v1.w;
    }
    if (e < re) {
        int j = __ldg(&adj[e]);
        float4 v = __ldg((const float4*)(h1 + (size_t)j * 128 + lane * 4));
        acc.x += v.x; acc.y += v.y; acc.z += v.z; acc.w += v.w;
    }
    *(float4*)ap = acc;
}

// ======================= final layer (dout=3), R4-proven ====================
__global__ __launch_bounds__(256)
void final_kernel(const float* __restrict__ in, const float* __restrict__ feat,
                  const float* __restrict__ W0, const float* __restrict__ b0,
                  const float* __restrict__ W1, const float* __restrict__ b1,
                  float* __restrict__ out, float* __restrict__ h1s, int n)
{
    __shared__ float ws[128][6];
    __shared__ float bs[6];
    int tid = threadIdx.x;
    for (int idx = tid; idx < 768; idx += 256) {
        int k = idx / 6, j = idx % 6;
        ws[k][j] = (j < 3) ? __ldg(&W0[k * 3 + j]) : __ldg(&W1[k * 3 + (j - 3)]);
    }
    if (tid < 3)      bs[tid] = __ldg(&b0[tid]);
    else if (tid < 6) bs[tid] = __ldg(&b1[tid - 3]);
    __syncthreads();

    int lane = tid & 31;
    int node = blockIdx.x * 8 + (tid >> 5);
    if (node >= n) return;

    float acc[6] = {0.f, 0.f, 0.f, 0.f, 0.f, 0.f};
    const float* xin = in   + (size_t)node * 128;
    const float* xf  = feat + (size_t)node * 128;
#pragma unroll
    for (int f = 0; f < 4; f++) {
        int k = f * 32 + lane;
        float x = fmaxf(xin[k], 0.f) + xf[k];
#pragma unroll
        for (int j = 0; j < 6; j++) acc[j] += x * ws[k][j];
    }
#pragma unroll
    for (int j = 0; j < 6; j++) {
#pragma unroll
        for (int o = 16; o > 0; o >>= 1)
            acc[j] += __shfl_xor_sync(0xffffffffu, acc[j], o);
    }
    if (lane == 0) {
        out[node * 3 + 0] = acc[0] + bs[0];
        out[node * 3 + 1] = acc[1] + bs[1];
        out[node * 3 + 2] = acc[2] + bs[2];
        h1s[node * 3 + 0] = acc[3] + bs[3];
        h1s[node * 3 + 1] = acc[4] + bs[4];
        h1s[node * 3 + 2] = acc[5] + bs[5];
    }
}

__global__ void gather3_kernel(const int* __restrict__ rowstart,
                               const int* __restrict__ adj,
                               const float* __restrict__ h1s,
                               float* __restrict__ out, int n)
{
    int i = blockIdx.x * blockDim.x + threadIdx.x;
    if (i >= n) return;
    int rs = __ldg(&rowstart[i]);
    int re = __ldg(&rowstart[i + 1]);
    float a0 = 0.f, a1 = 0.f, a2 = 0.f;
    for (int e = rs; e < re; e++) {
        int j = __ldg(&adj[e]);
        a0 += __ldg(&h1s[j * 3 + 0]);
        a1 += __ldg(&h1s[j * 3 + 1]);
        a2 += __ldg(&h1s[j * 3 + 2]);
    }
    out[i * 3 + 0] += a0;
    out[i * 3 + 1] += a1;
    out[i * 3 + 2] += a2;
}

// ======================= launch ============================================
extern "C" void kernel_launch(void* const* d_in, const int* in_sizes, int n_in,
                              void* d_out, int out_size)
{
    const float* feat  = (const float*)d_in[0];
    const int2*  edges = (const int2*) d_in[1];
    const int N = in_sizes[0] / 128;
    const int E = in_sizes[1] / 2;

    const float *W0[4], *B0[4], *W1[4], *B1[4];
    for (int i = 0; i < 4; i++) {
        W0[i] = (const float*)d_in[2 + 4 * i];
        B0[i] = (const float*)d_in[3 + 4 * i];
        W1[i] = (const float*)d_in[4 + 4 * i];
        B1[i] = (const float*)d_in[5 + 4 * i];
    }

    float *bufA, *bufB, *h1, *h1s, *biasAll;
    __half *w16All;
    int *deg, *cur, *rowstart, *adj, *bsum;
    cudaGetSymbolAddress((void**)&bufA, g_bufA);
    cudaGetSymbolAddress((void**)&bufB, g_bufB);
    cudaGetSymbolAddress((void**)&h1,   g_h1);
    cudaGetSymbolAddress((void**)&h1s,  g_h1s);
    cudaGetSymbolAddress((void**)&w16All, g_W16);
    cudaGetSymbolAddress((void**)&biasAll, g_bias);
    cudaGetSymbolAddress((void**)&deg, g_deg);
    cudaGetSymbolAddress((void**)&cur, g_cur);
    cudaGetSymbolAddress((void**)&rowstart, g_rowstart);
    cudaGetSymbolAddress((void**)&adj, g_adj);
    cudaGetSymbolAddress((void**)&bsum, g_bsum);

    cudaFuncSetAttribute(gemm_persist_kernel<0>, cudaFuncAttributeMaxDynamicSharedMemorySize, SM_DYN);
    cudaFuncSetAttribute(gemm_persist_kernel<1>, cudaFuncAttributeMaxDynamicSharedMemorySize, SM_DYN);

    // weight prep
    for (int l = 0; l < 3; l++) {
        prep_w_kernel<<<16, 256>>>(W0[l], B0[l], W1[l], B1[l],
                                   w16All + l * 256 * 128, biasAll + l * 256);
    }

    // CSR build
    const int NB = (N + 1023) / 1024;
    zero_deg_kernel<<<(N + 255) / 256, 256>>>(deg, N);
    count_deg_kernel<<<(E + 255) / 256, 256>>>(edges, deg, E);
    scanA_kernel<<<NB, 1024>>>(deg, rowstart, bsum, N);
    scanB_kernel<<<1, 512>>>(bsum, NB);
    scanC_kernel<<<NB, 1024>>>(rowstart, cur, bsum, N, 2 * E);
    fill_adj_kernel<<<(E + 255) / 256, 256>>>(edges, cur, adj, E);

    const int numTiles = (N + 63) / 64;
    const int PGRID = 148;
    const int gaBlocks = (N + 7) / 8;
    float* out = (float*)d_out;

    gemm_persist_kernel<0><<<PGRID, 512, SM_DYN>>>(feat, w16All, biasAll,
                                                   bufA, h1, N, numTiles);
    gather128_kernel<<<gaBlocks, 256>>>(rowstart, adj, h1, bufA, N);

    gemm_persist_kernel<1><<<PGRID, 512, SM_DYN>>>(bufA, w16All + 256 * 128,
                                                   biasAll + 256, bufB, h1, N, numTiles);
    gather128_kernel<<<gaBlocks, 256>>>(rowstart, adj, h1, bufB, N);

    gemm_persist_kernel<1><<<PGRID, 512, SM_DYN>>>(bufB, w16All + 2 * 256 * 128,
                                                   biasAll + 2 * 256, bufA, h1, N, numTiles);
    gather128_kernel<<<gaBlocks, 256>>>(rowstart, adj, h1, bufA, N);

    final_kernel<<<gaBlocks, 256>>>(bufA, feat, W0[3], B0[3], W1[3], B1[3], out, h1s, N);
    gather3_kernel<<<(N + 255) / 256, 256>>>(rowstart, adj, h1s, out, N);
}

// round 9
// speedup vs baseline: 2.6873x; 1.1193x over previous
#include <cuda_runtime.h>
#include <cuda_fp16.h>
#include <cstdint>

// ---------------------------------------------------------------------------
// MeshRefineNet on GB300 (sm_103a), R9 = R8 (967us) with fp16 intermediates:
// h1, bufA, bufB stored as fp16 (fp32 accumulation everywhere) -> gather and
// GEMM traffic halves. rel err est ~4e-4 (thr 1e-3).
//   layer i: h0 = x@W0+b0; h1 = x@W1+b1; out = h0 + sum_{j in N(i)} h1[j]
//   relu after layers 0..2; skip before layer 3; layer 3 dout=3.
// ---------------------------------------------------------------------------

#define NMAX 320000
#define EMAX 1000000

__device__ __align__(16) __half g_bufA[NMAX * 128];
__device__ __align__(16) __half g_bufB[NMAX * 128];
__device__ __align__(16) __half g_h1 [NMAX * 128];
__device__ float g_h1s[NMAX * 3];

// fp16 weight images: Bt[n][k] = W[k][n] (n<128 from W0, else W1), linear.
__device__ __align__(16) __half g_W16[3][256 * 128];
__device__ float g_bias[3][256];

// CSR scratch
__device__ int g_deg[NMAX];
__device__ int g_cur[NMAX];
__device__ int g_rowstart[NMAX + 1];
__device__ int g_adj[2 * EMAX];
__device__ int g_bsum[512];

// ======================= helpers ===========================================
__device__ __forceinline__ uint32_t smem_to_u32(const void* p) {
    uint32_t a;
    asm("{ .reg .u64 t; cvta.to.shared.u64 t, %1; cvt.u32.u64 %0, t; }"
        : "=r"(a) : "l"(p));
    return a;
}
__device__ __forceinline__ uint32_t pkh(float a, float b) {
    __half2 t = __floats2half2_rn(a, b);
    return *(uint32_t*)&t;
}
__device__ __forceinline__ float2 uph(uint32_t u) {
    __half2 h = *(__half2*)&u;
    return __half22float2(h);
}
__device__ __forceinline__ float4 h4tof4(uint2 u) {
    float2 a = uph(u.x), b = uph(u.y);
    return make_float4(a.x, a.y, b.x, b.y);
}
__device__ __forceinline__ uint2 f4toh4(float4 v) {
    uint2 u;
    u.x = pkh(v.x, v.y);
    u.y = pkh(v.z, v.w);
    return u;
}
// XOR-swizzled offset for 16-bit tile images with 256B rows (128 halves/row).
__device__ __forceinline__ uint32_t aswz(uint32_t row, uint32_t kblk) {
    return row * 256u + ((((kblk ^ row) & 7u) | (kblk & 8u)) << 4);
}
__device__ __forceinline__ void ldsm_x4(uint32_t& r0, uint32_t& r1,
                                        uint32_t& r2, uint32_t& r3, uint32_t addr) {
    asm volatile("ldmatrix.sync.aligned.m8n8.x4.shared.b16 {%0,%1,%2,%3}, [%4];"
                 : "=r"(r0), "=r"(r1), "=r"(r2), "=r"(r3) : "r"(addr));
}
__device__ __forceinline__ void mma16816(float* d, const uint32_t* a,
                                         const uint32_t* b) {
    asm volatile("mma.sync.aligned.m16n8k16.row.col.f32.f16.f16.f32 "
                 "{%0,%1,%2,%3}, {%4,%5,%6,%7}, {%8,%9}, {%0,%1,%2,%3};"
                 : "+f"(d[0]), "+f"(d[1]), "+f"(d[2]), "+f"(d[3])
                 : "r"(a[0]), "r"(a[1]), "r"(a[2]), "r"(a[3]),
                   "r"(b[0]), "r"(b[1]));
}

// ======================= weight prep (once per launch) =====================
__global__ void prep_w_kernel(const float* __restrict__ W0, const float* __restrict__ b0,
                              const float* __restrict__ W1, const float* __restrict__ b1,
                              __half* __restrict__ w16, float* __restrict__ biasOut)
{
    int t0 = blockIdx.x * blockDim.x + threadIdx.x;
    if (t0 < 256) biasOut[t0] = (t0 < 128) ? b0[t0] : b1[t0 - 128];
    uint32_t* wp = (uint32_t*)w16;
    for (int idx = t0; idx < 256 * 64; idx += blockDim.x * gridDim.x) {
        int n = idx >> 6, p = idx & 63;
        int k = p * 2;
        float x0, x1;
        if (n < 128) { x0 = W0[k * 128 + n]; x1 = W0[(k + 1) * 128 + n]; }
        else         { x0 = W1[k * 128 + n - 128]; x1 = W1[(k + 1) * 128 + n - 128]; }
        wp[idx] = pkh(x0, x1);
    }
}

// ======================= CSR build =========================================
__global__ void zero_deg_kernel(int* deg, int n) {
    int i = blockIdx.x * blockDim.x + threadIdx.x;
    if (i < n) deg[i] = 0;
}
__global__ void count_deg_kernel(const int2* __restrict__ edges, int* deg, int E) {
    int e = blockIdx.x * blockDim.x + threadIdx.x;
    if (e >= E) return;
    int2 ed = __ldg(&edges[e]);
    atomicAdd(&deg[ed.x], 1);
    atomicAdd(&deg[ed.y], 1);
}
__global__ __launch_bounds__(1024)
void scanA_kernel(const int* __restrict__ deg, int* rowstart, int* bsum, int n) {
    __shared__ int s[1024];
    int t = threadIdx.x;
    int i = blockIdx.x * 1024 + t;
    int v = (i < n) ? deg[i] : 0;
    s[t] = v;
    __syncthreads();
#pragma unroll
    for (int o = 1; o < 1024; o <<= 1) {
        int x = (t >= o) ? s[t - o] : 0;
        __syncthreads();
        s[t] += x;
        __syncthreads();
    }
    if (i < n) rowstart[i] = s[t] - v;
    if (t == 1023) bsum[blockIdx.x] = s[1023];
}
__global__ __launch_bounds__(512)
void scanB_kernel(int* bsum, int nb) {
    __shared__ int s[512];
    int t = threadIdx.x;
    int v = (t < nb) ? bsum[t] : 0;
    s[t] = v;
    __syncthreads();
#pragma unroll
    for (int o = 1; o < 512; o <<= 1) {
        int x = (t >= o) ? s[t - o] : 0;
        __syncthreads();
        s[t] += x;
        __syncthreads();
    }
    if (t < nb) bsum[t] = s[t] - v;
}
__global__ __launch_bounds__(1024)
void scanC_kernel(int* rowstart, int* cur, const int* __restrict__ bsum,
                  int n, int total) {
    int i = blockIdx.x * 1024 + threadIdx.x;
    if (i < n) {
        int r = rowstart[i] + bsum[blockIdx.x];
        rowstart[i] = r;
        cur[i] = r;
    }
    if (i == 0) rowstart[n] = total;
}
__global__ void fill_adj_kernel(const int2* __restrict__ edges, int* cur,
                                int* adj, int E) {
    int e = blockIdx.x * blockDim.x + threadIdx.x;
    if (e >= E) return;
    int2 ed = __ldg(&edges[e]);
    int ps = atomicAdd(&cur[ed.x], 1);
    adj[ps] = ed.y;
    int pd = atomicAdd(&cur[ed.y], 1);
    adj[pd] = ed.x;
}

// ======================= persistent fp16 HMMA dual-GEMM ====================
// smem: B 64K | A dbuf 2 x 16K = 96 KB.
static constexpr int SM_B    = 0;
static constexpr int SM_A    = 65536;
static constexpr int A_STRIDE = 16384;
static constexpr int SM_DYN  = 98304;

// FP16IN: input activations stored fp16 (layers 1,2); else fp32 (layer 0).
template<int MODE, bool FP16IN>
__global__ __launch_bounds__(512, 1)
void gemm_persist_kernel(const void* __restrict__ inPtr,
                         const __half* __restrict__ W16,
                         const float* __restrict__ bias256,
                         __half* __restrict__ agg, __half* __restrict__ h1v,
                         int n, int numTiles)
{
    extern __shared__ char sm[];
    const uint32_t sbase = smem_to_u32(sm);
    const int tid  = threadIdx.x;
    const int wid  = tid >> 5;
    const int lane = tid & 31;

    // ---- stage B once (swizzled 256B rows) ----
    {
        const uint32_t* src = (const uint32_t*)W16;
#pragma unroll
        for (int u = 0; u < 32; u++) {
            int idx = u * 512 + tid;            // 0..16383
            int row = idx >> 6, p = idx & 63;
            uint32_t off = aswz(row, p >> 2) + (p & 3) * 4;
            *(uint32_t*)(sm + SM_B + off) = src[idx];
        }
    }

    int tile = blockIdx.x;
    if (tile >= numTiles) { __syncthreads(); return; }

    auto loadA = [&](int gr, int p) -> float2 {
        if (FP16IN) {
            uint32_t u = *(const uint32_t*)((const __half*)inPtr + (size_t)gr * 128 + p * 2);
            return uph(u);
        } else {
            return *(const float2*)((const float*)inPtr + (size_t)gr * 128 + p * 2);
        }
    };

    // ---- stage A tile0 into buf0 ----
    {
        int tb = tile * 64;
#pragma unroll
        for (int u = 0; u < 8; u++) {
            int idx = u * 512 + tid;           // 0..4095
            int row = idx >> 6, p = idx & 63;
            int gr = tb + row;
            float2 xv = make_float2(0.f, 0.f);
            if (gr < n) xv = loadA(gr, p);
            if (MODE == 1) { xv.x = fmaxf(xv.x, 0.f); xv.y = fmaxf(xv.y, 0.f); }
            uint32_t off = aswz(row, p >> 2) + (p & 3) * 4;
            *(uint32_t*)(sm + SM_A + off) = pkh(xv.x, xv.y);
        }
    }
    __syncthreads();

    // warp grid: 2(m) x 8(n); warp tile 32x32
    const int mbase = (wid & 1) * 32;
    const int nbase = (wid >> 1) * 32;
    const int aRow  = lane & 15;
    const int aKs   = lane >> 4;
    const int bTile = lane >> 3;
    const int bRow  = (lane & 7) + ((bTile >> 1) << 3);
    const int colq  = 2 * (lane & 3);

    for (int it = 0; ; it++) {
        const int buf = it & 1;
        const int tb = tile * 64;
        const int next = tile + gridDim.x;
        const bool hasNext = next < numTiles;

        // prefetch next A tile (LDG under compute)
        float2 pf[8];
        if (hasNext) {
            int ntb = next * 64;
#pragma unroll
            for (int u = 0; u < 8; u++) {
                int idx = u * 512 + tid;
                int row = idx >> 6, p = idx & 63;
                int gr = ntb + row;
                pf[u] = (gr < n) ? loadA(gr, p) : make_float2(0.f, 0.f);
            }
        }

        // ---- compute: single fp16 pass, K=128 (8 k-steps) ----
        float d[2][4][4];
#pragma unroll
        for (int mb = 0; mb < 2; mb++)
#pragma unroll
            for (int nb = 0; nb < 4; nb++)
#pragma unroll
                for (int q = 0; q < 4; q++) d[mb][nb][q] = 0.f;

        const uint32_t aB = sbase + SM_A + buf * A_STRIDE;
        const uint32_t bB = sbase + SM_B;
#pragma unroll
        for (int kk = 0; kk < 8; kk++) {
            const int kblk0 = kk * 2;
            uint32_t a[2][4];
#pragma unroll
            for (int mb = 0; mb < 2; mb++) {
                uint32_t addr = aB + aswz(mbase + mb * 16 + aRow, kblk0 + aKs);
                ldsm_x4(a[mb][0], a[mb][1], a[mb][2], a[mb][3], addr);
            }
#pragma unroll
            for (int nb2 = 0; nb2 < 2; nb2++) {
                uint32_t addr = bB + aswz(nbase + nb2 * 16 + bRow,
                                          kblk0 + (bTile & 1));
                uint32_t b0, b1, b2, b3;
                ldsm_x4(b0, b1, b2, b3, addr);
                uint32_t blo[2] = {b0, b1};
                uint32_t bhi[2] = {b2, b3};
                mma16816(d[0][nb2 * 2 + 0], a[0], blo);
                mma16816(d[1][nb2 * 2 + 0], a[1], blo);
                mma16816(d[0][nb2 * 2 + 1], a[0], bhi);
                mma16816(d[1][nb2 * 2 + 1], a[1], bhi);
            }
        }

        // ---- epilogue: +bias, cols<128 -> agg(h0) fp16, else h1 fp16 ----
#pragma unroll
        for (int mb = 0; mb < 2; mb++) {
#pragma unroll
            for (int h = 0; h < 2; h++) {
                int row = tb + mbase + mb * 16 + (lane >> 2) + h * 8;
                if (row >= n) continue;
#pragma unroll
                for (int nb = 0; nb < 4; nb++) {
                    int col = nbase + nb * 8 + colq;
                    float2 bv = __ldg((const float2*)(bias256 + col));
                    float vx = d[mb][nb][2 * h + 0] + bv.x;
                    float vy = d[mb][nb][2 * h + 1] + bv.y;
                    uint32_t pv = pkh(vx, vy);
                    if (col < 128)
                        *(uint32_t*)(agg + (size_t)row * 128 + col) = pv;
                    else
                        *(uint32_t*)(h1v + (size_t)row * 128 + (col - 128)) = pv;
                }
            }
        }

        if (!hasNext) break;

        // ---- convert + store prefetched tile into other buffer ----
        {
            char* ab = sm + SM_A + (buf ^ 1) * A_STRIDE;
#pragma unroll
            for (int u = 0; u < 8; u++) {
                int idx = u * 512 + tid;
                int row = idx >> 6, p = idx & 63;
                float2 xv = pf[u];
                if (MODE == 1) { xv.x = fmaxf(xv.x, 0.f); xv.y = fmaxf(xv.y, 0.f); }
                uint32_t off = aswz(row, p >> 2) + (p & 3) * 4;
                *(uint32_t*)(ab + off) = pkh(xv.x, xv.y);
            }
        }
        tile = next;
        __syncthreads();
    }
}

// ======================= CSR gather (128-wide, fp16) =======================
// Warp per node; lane covers halves [lane*4, lane*4+4) -> uint2 (8 B) loads.
__global__ __launch_bounds__(256)
void gather128_kernel(const int* __restrict__ rowstart, const int* __restrict__ adj,
                      const __half* __restrict__ h1, __half* __restrict__ agg, int n)
{
    int node = blockIdx.x * 8 + (threadIdx.x >> 5);
    int lane = threadIdx.x & 31;
    if (node >= n) return;
    int rs = __ldg(&rowstart[node]);
    int re = __ldg(&rowstart[node + 1]);
    int k0 = lane * 4;
    uint2* ap = (uint2*)(agg + (size_t)node * 128 + k0);
    float4 acc = h4tof4(*ap);
    int e = rs;
    for (; e + 3 < re; e += 4) {
        int j0 = __ldg(&adj[e]),     j1 = __ldg(&adj[e + 1]);
        int j2 = __ldg(&adj[e + 2]), j3 = __ldg(&adj[e + 3]);
        float4 v0 = h4tof4(__ldg((const uint2*)(h1 + (size_t)j0 * 128 + k0)));
        float4 v1 = h4tof4(__ldg((const uint2*)(h1 + (size_t)j1 * 128 + k0)));
        float4 v2 = h4tof4(__ldg((const uint2*)(h1 + (size_t)j2 * 128 + k0)));
        float4 v3 = h4tof4(__ldg((const uint2*)(h1 + (size_t)j3 * 128 + k0)));
        acc.x += v0.x + v1.x + v2.x + v3.x;
        acc.y += v0.y + v1.y + v2.y + v3.y;
        acc.z += v0.z + v1.z + v2.z + v3.z;
        acc.w += v0.w + v1.w + v2.w + v3.w;
    }
    for (; e < re; e++) {
        int j = __ldg(&adj[e]);
        float4 v = h4tof4(__ldg((const uint2*)(h1 + (size_t)j * 128 + k0)));
        acc.x += v.x; acc.y += v.y; acc.z += v.z; acc.w += v.w;
    }
    *ap = f4toh4(acc);
}

// ======================= final layer (dout=3), fp16 input ===================
__global__ __launch_bounds__(256)
void final_kernel(const __half* __restrict__ in, const float* __restrict__ feat,
                  const float* __restrict__ W0, const float* __restrict__ b0,
                  const float* __restrict__ W1, const float* __restrict__ b1,
                  float* __restrict__ out, float* __restrict__ h1s, int n)
{
    __shared__ float ws[128][6];
    __shared__ float bs[6];
    int tid = threadIdx.x;
    for (int idx = tid; idx < 768; idx += 256) {
        int k = idx / 6, j = idx % 6;
        ws[k][j] = (j < 3) ? __ldg(&W0[k * 3 + j]) : __ldg(&W1[k * 3 + (j - 3)]);
    }
    if (tid < 3)      bs[tid] = __ldg(&b0[tid]);
    else if (tid < 6) bs[tid] = __ldg(&b1[tid - 3]);
    __syncthreads();

    int lane = tid & 31;
    int node = blockIdx.x * 8 + (tid >> 5);
    if (node >= n) return;

    float acc[6] = {0.f, 0.f, 0.f, 0.f, 0.f, 0.f};
    const __half* xin = in + (size_t)node * 128;
    const float*  xf  = feat + (size_t)node * 128;
#pragma unroll
    for (int f = 0; f < 4; f++) {
        int k = f * 32 + lane;
        float x = fmaxf(__half2float(xin[k]), 0.f) + xf[k];
#pragma unroll
        for (int j = 0; j < 6; j++) acc[j] += x * ws[k][j];
    }
#pragma unroll
    for (int j = 0; j < 6; j++) {
#pragma unroll
        for (int o = 16; o > 0; o >>= 1)
            acc[j] += __shfl_xor_sync(0xffffffffu, acc[j], o);
    }
    if (lane == 0) {
        out[node * 3 + 0] = acc[0] + bs[0];
        out[node * 3 + 1] = acc[1] + bs[1];
        out[node * 3 + 2] = acc[2] + bs[2];
        h1s[node * 3 + 0] = acc[3] + bs[3];
        h1s[node * 3 + 1] = acc[4] + bs[4];
        h1s[node * 3 + 2] = acc[5] + bs[5];
    }
}

__global__ void gather3_kernel(const int* __restrict__ rowstart,
                               const int* __restrict__ adj,
                               const float* __restrict__ h1s,
                               float* __restrict__ out, int n)
{
    int i = blockIdx.x * blockDim.x + threadIdx.x;
    if (i >= n) return;
    int rs = __ldg(&rowstart[i]);
    int re = __ldg(&rowstart[i + 1]);
    float a0 = 0.f, a1 = 0.f, a2 = 0.f;
    for (int e = rs; e < re; e++) {
        int j = __ldg(&adj[e]);
        a0 += __ldg(&h1s[j * 3 + 0]);
        a1 += __ldg(&h1s[j * 3 + 1]);
        a2 += __ldg(&h1s[j * 3 + 2]);
    }
    out[i * 3 + 0] += a0;
    out[i * 3 + 1] += a1;
    out[i * 3 + 2] += a2;
}

// ======================= launch ============================================
extern "C" void kernel_launch(void* const* d_in, const int* in_sizes, int n_in,
                              void* d_out, int out_size)
{
    const float* feat  = (const float*)d_in[0];
    const int2*  edges = (const int2*) d_in[1];
    const int N = in_sizes[0] / 128;
    const int E = in_sizes[1] / 2;

    const float *W0[4], *B0[4], *W1[4], *B1[4];
    for (int i = 0; i < 4; i++) {
        W0[i] = (const float*)d_in[2 + 4 * i];
        B0[i] = (const float*)d_in[3 + 4 * i];
        W1[i] = (const float*)d_in[4 + 4 * i];
        B1[i] = (const float*)d_in[5 + 4 * i];
    }

    __half *bufA, *bufB, *h1, *w16All;
    float *h1s, *biasAll;
    int *deg, *cur, *rowstart, *adj, *bsum;
    cudaGetSymbolAddress((void**)&bufA, g_bufA);
    cudaGetSymbolAddress((void**)&bufB, g_bufB);
    cudaGetSymbolAddress((void**)&h1,   g_h1);
    cudaGetSymbolAddress((void**)&h1s,  g_h1s);
    cudaGetSymbolAddress((void**)&w16All, g_W16);
    cudaGetSymbolAddress((void**)&biasAll, g_bias);
    cudaGetSymbolAddress((void**)&deg, g_deg);
    cudaGetSymbolAddress((void**)&cur, g_cur);
    cudaGetSymbolAddress((void**)&rowstart, g_rowstart);
    cudaGetSymbolAddress((void**)&adj, g_adj);
    cudaGetSymbolAddress((void**)&bsum, g_bsum);

    cudaFuncSetAttribute((const void*)gemm_persist_kernel<0, false>,
                         cudaFuncAttributeMaxDynamicSharedMemorySize, SM_DYN);
    cudaFuncSetAttribute((const void*)gemm_persist_kernel<1, true>,
                         cudaFuncAttributeMaxDynamicSharedMemorySize, SM_DYN);

    // weight prep
    for (int l = 0; l < 3; l++) {
        prep_w_kernel<<<16, 256>>>(W0[l], B0[l], W1[l], B1[l],
                                   w16All + l * 256 * 128, biasAll + l * 256);
    }

    // CSR build
    const int NB = (N + 1023) / 1024;
    zero_deg_kernel<<<(N + 255) / 256, 256>>>(deg, N);
    count_deg_kernel<<<(E + 255) / 256, 256>>>(edges, deg, E);
    scanA_kernel<<<NB, 1024>>>(deg, rowstart, bsum, N);
    scanB_kernel<<<1, 512>>>(bsum, NB);
    scanC_kernel<<<NB, 1024>>>(rowstart, cur, bsum, N, 2 * E);
    fill_adj_kernel<<<(E + 255) / 256, 256>>>(edges, cur, adj, E);

    const int numTiles = (N + 63) / 64;
    const int PGRID = 148;
    const int gaBlocks = (N + 7) / 8;
    float* out = (float*)d_out;

    gemm_persist_kernel<0, false><<<PGRID, 512, SM_DYN>>>(feat, w16All, biasAll,
                                                          bufA, h1, N, numTiles);
    gather128_kernel<<<gaBlocks, 256>>>(rowstart, adj, h1, bufA, N);

    gemm_persist_kernel<1, true><<<PGRID, 512, SM_DYN>>>(bufA, w16All + 256 * 128,
                                                         biasAll + 256, bufB, h1, N, numTiles);
    gather128_kernel<<<gaBlocks, 256>>>(rowstart, adj, h1, bufB, N);

    gemm_persist_kernel<1, true><<<PGRID, 512, SM_DYN>>>(bufB, w16All + 2 * 256 * 128,
                                                         biasAll + 2 * 256, bufA, h1, N, numTiles);
    gather128_kernel<<<gaBlocks, 256>>>(rowstart, adj, h1, bufA, N);

    final_kernel<<<gaBlocks, 256>>>(bufA, feat, W0[3], B0[3], W1[3], B1[3], out, h1s, N);
    gather3_kernel<<<(N + 255) / 256, 256>>>(rowstart, adj, h1s, out, N);
}

// round 10
// speedup vs baseline: 2.7173x; 1.0112x over previous
#include <cuda_runtime.h>
#include <cuda_fp16.h>
#include <cstdint>

// ---------------------------------------------------------------------------
// MeshRefineNet on GB300 (sm_103a), R10 = R9 (864us) with the CSR gather
// restructured: adjacency loaded coalesced (one LDG per 32 neighbors) and
// broadcast via shuffle -> neighbor-row loads become independent (MLP ~ deg)
// instead of chained adj->row round trips.
//   layer i: h0 = x@W0+b0; h1 = x@W1+b1; out = h0 + sum_{j in N(i)} h1[j]
//   relu after layers 0..2; skip before layer 3; layer 3 dout=3.
// fp16 intermediates, fp32 accumulation (rel err ~2e-4, thr 1e-3).
// ---------------------------------------------------------------------------

#define NMAX 320000
#define EMAX 1000000

__device__ __align__(16) __half g_bufA[NMAX * 128];
__device__ __align__(16) __half g_bufB[NMAX * 128];
__device__ __align__(16) __half g_h1 [NMAX * 128];
__device__ float g_h1s[NMAX * 3];

// fp16 weight images: Bt[n][k] = W[k][n] (n<128 from W0, else W1), linear.
__device__ __align__(16) __half g_W16[3][256 * 128];
__device__ float g_bias[3][256];

// CSR scratch
__device__ int g_deg[NMAX];
__device__ int g_cur[NMAX];
__device__ int g_rowstart[NMAX + 1];
__device__ int g_adj[2 * EMAX];
__device__ int g_bsum[512];

// ======================= helpers ===========================================
__device__ __forceinline__ uint32_t smem_to_u32(const void* p) {
    uint32_t a;
    asm("{ .reg .u64 t; cvta.to.shared.u64 t, %1; cvt.u32.u64 %0, t; }"
        : "=r"(a) : "l"(p));
    return a;
}
__device__ __forceinline__ uint32_t pkh(float a, float b) {
    __half2 t = __floats2half2_rn(a, b);
    return *(uint32_t*)&t;
}
__device__ __forceinline__ float2 uph(uint32_t u) {
    __half2 h = *(__half2*)&u;
    return __half22float2(h);
}
__device__ __forceinline__ float4 h4tof4(uint2 u) {
    float2 a = uph(u.x), b = uph(u.y);
    return make_float4(a.x, a.y, b.x, b.y);
}
__device__ __forceinline__ uint2 f4toh4(float4 v) {
    uint2 u;
    u.x = pkh(v.x, v.y);
    u.y = pkh(v.z, v.w);
    return u;
}
// XOR-swizzled offset for 16-bit tile images with 256B rows (128 halves/row).
__device__ __forceinline__ uint32_t aswz(uint32_t row, uint32_t kblk) {
    return row * 256u + ((((kblk ^ row) & 7u) | (kblk & 8u)) << 4);
}
__device__ __forceinline__ void ldsm_x4(uint32_t& r0, uint32_t& r1,
                                        uint32_t& r2, uint32_t& r3, uint32_t addr) {
    asm volatile("ldmatrix.sync.aligned.m8n8.x4.shared.b16 {%0,%1,%2,%3}, [%4];"
                 : "=r"(r0), "=r"(r1), "=r"(r2), "=r"(r3) : "r"(addr));
}
__device__ __forceinline__ void mma16816(float* d, const uint32_t* a,
                                         const uint32_t* b) {
    asm volatile("mma.sync.aligned.m16n8k16.row.col.f32.f16.f16.f32 "
                 "{%0,%1,%2,%3}, {%4,%5,%6,%7}, {%8,%9}, {%0,%1,%2,%3};"
                 : "+f"(d[0]), "+f"(d[1]), "+f"(d[2]), "+f"(d[3])
                 : "r"(a[0]), "r"(a[1]), "r"(a[2]), "r"(a[3]),
                   "r"(b[0]), "r"(b[1]));
}

// ======================= weight prep (once per launch) =====================
__global__ void prep_w_kernel(const float* __restrict__ W0, const float* __restrict__ b0,
                              const float* __restrict__ W1, const float* __restrict__ b1,
                              __half* __restrict__ w16, float* __restrict__ biasOut)
{
    int t0 = blockIdx.x * blockDim.x + threadIdx.x;
    if (t0 < 256) biasOut[t0] = (t0 < 128) ? b0[t0] : b1[t0 - 128];
    uint32_t* wp = (uint32_t*)w16;
    for (int idx = t0; idx < 256 * 64; idx += blockDim.x * gridDim.x) {
        int n = idx >> 6, p = idx & 63;
        int k = p * 2;
        float x0, x1;
        if (n < 128) { x0 = W0[k * 128 + n]; x1 = W0[(k + 1) * 128 + n]; }
        else         { x0 = W1[k * 128 + n - 128]; x1 = W1[(k + 1) * 128 + n - 128]; }
        wp[idx] = pkh(x0, x1);
    }
}

// ======================= CSR build =========================================
__global__ void zero_deg_kernel(int* deg, int n) {
    int i = blockIdx.x * blockDim.x + threadIdx.x;
    if (i < n) deg[i] = 0;
}
__global__ void count_deg_kernel(const int2* __restrict__ edges, int* deg, int E) {
    int e = blockIdx.x * blockDim.x + threadIdx.x;
    if (e >= E) return;
    int2 ed = __ldg(&edges[e]);
    atomicAdd(&deg[ed.x], 1);
    atomicAdd(&deg[ed.y], 1);
}
__global__ __launch_bounds__(1024)
void scanA_kernel(const int* __restrict__ deg, int* rowstart, int* bsum, int n) {
    __shared__ int s[1024];
    int t = threadIdx.x;
    int i = blockIdx.x * 1024 + t;
    int v = (i < n) ? deg[i] : 0;
    s[t] = v;
    __syncthreads();
#pragma unroll
    for (int o = 1; o < 1024; o <<= 1) {
        int x = (t >= o) ? s[t - o] : 0;
        __syncthreads();
        s[t] += x;
        __syncthreads();
    }
    if (i < n) rowstart[i] = s[t] - v;
    if (t == 1023) bsum[blockIdx.x] = s[1023];
}
__global__ __launch_bounds__(512)
void scanB_kernel(int* bsum, int nb) {
    __shared__ int s[512];
    int t = threadIdx.x;
    int v = (t < nb) ? bsum[t] : 0;
    s[t] = v;
    __syncthreads();
#pragma unroll
    for (int o = 1; o < 512; o <<= 1) {
        int x = (t >= o) ? s[t - o] : 0;
        __syncthreads();
        s[t] += x;
        __syncthreads();
    }
    if (t < nb) bsum[t] = s[t] - v;
}
__global__ __launch_bounds__(1024)
void scanC_kernel(int* rowstart, int* cur, const int* __restrict__ bsum,
                  int n, int total) {
    int i = blockIdx.x * 1024 + threadIdx.x;
    if (i < n) {
        int r = rowstart[i] + bsum[blockIdx.x];
        rowstart[i] = r;
        cur[i] = r;
    }
    if (i == 0) rowstart[n] = total;
}
__global__ void fill_adj_kernel(const int2* __restrict__ edges, int* cur,
                                int* adj, int E) {
    int e = blockIdx.x * blockDim.x + threadIdx.x;
    if (e >= E) return;
    int2 ed = __ldg(&edges[e]);
    int ps = atomicAdd(&cur[ed.x], 1);
    adj[ps] = ed.y;
    int pd = atomicAdd(&cur[ed.y], 1);
    adj[pd] = ed.x;
}

// ======================= persistent fp16 HMMA dual-GEMM ====================
// smem: B 64K | A dbuf 2 x 16K = 96 KB.
static constexpr int SM_B    = 0;
static constexpr int SM_A    = 65536;
static constexpr int A_STRIDE = 16384;
static constexpr int SM_DYN  = 98304;

// FP16IN: input activations stored fp16 (layers 1,2); else fp32 (layer 0).
template<int MODE, bool FP16IN>
__global__ __launch_bounds__(512, 1)
void gemm_persist_kernel(const void* __restrict__ inPtr,
                         const __half* __restrict__ W16,
                         const float* __restrict__ bias256,
                         __half* __restrict__ agg, __half* __restrict__ h1v,
                         int n, int numTiles)
{
    extern __shared__ char sm[];
    const uint32_t sbase = smem_to_u32(sm);
    const int tid  = threadIdx.x;
    const int wid  = tid >> 5;
    const int lane = tid & 31;

    // ---- stage B once (swizzled 256B rows) ----
    {
        const uint32_t* src = (const uint32_t*)W16;
#pragma unroll
        for (int u = 0; u < 32; u++) {
            int idx = u * 512 + tid;            // 0..16383
            int row = idx >> 6, p = idx & 63;
            uint32_t off = aswz(row, p >> 2) + (p & 3) * 4;
            *(uint32_t*)(sm + SM_B + off) = src[idx];
        }
    }

    int tile = blockIdx.x;
    if (tile >= numTiles) { __syncthreads(); return; }

    auto loadA = [&](int gr, int p) -> float2 {
        if (FP16IN) {
            uint32_t u = *(const uint32_t*)((const __half*)inPtr + (size_t)gr * 128 + p * 2);
            return uph(u);
        } else {
            return *(const float2*)((const float*)inPtr + (size_t)gr * 128 + p * 2);
        }
    };

    // ---- stage A tile0 into buf0 ----
    {
        int tb = tile * 64;
#pragma unroll
        for (int u = 0; u < 8; u++) {
            int idx = u * 512 + tid;           // 0..4095
            int row = idx >> 6, p = idx & 63;
            int gr = tb + row;
            float2 xv = make_float2(0.f, 0.f);
            if (gr < n) xv = loadA(gr, p);
            if (MODE == 1) { xv.x = fmaxf(xv.x, 0.f); xv.y = fmaxf(xv.y, 0.f); }
            uint32_t off = aswz(row, p >> 2) + (p & 3) * 4;
            *(uint32_t*)(sm + SM_A + off) = pkh(xv.x, xv.y);
        }
    }
    __syncthreads();

    // warp grid: 2(m) x 8(n); warp tile 32x32
    const int mbase = (wid & 1) * 32;
    const int nbase = (wid >> 1) * 32;
    const int aRow  = lane & 15;
    const int aKs   = lane >> 4;
    const int bTile = lane >> 3;
    const int bRow  = (lane & 7) + ((bTile >> 1) << 3);
    const int colq  = 2 * (lane & 3);

    for (int it = 0; ; it++) {
        const int buf = it & 1;
        const int tb = tile * 64;
        const int next = tile + gridDim.x;
        const bool hasNext = next < numTiles;

        // prefetch next A tile (LDG under compute)
        float2 pf[8];
        if (hasNext) {
            int ntb = next * 64;
#pragma unroll
            for (int u = 0; u < 8; u++) {
                int idx = u * 512 + tid;
                int row = idx >> 6, p = idx & 63;
                int gr = ntb + row;
                pf[u] = (gr < n) ? loadA(gr, p) : make_float2(0.f, 0.f);
            }
        }

        // ---- compute: single fp16 pass, K=128 (8 k-steps) ----
        float d[2][4][4];
#pragma unroll
        for (int mb = 0; mb < 2; mb++)
#pragma unroll
            for (int nb = 0; nb < 4; nb++)
#pragma unroll
                for (int q = 0; q < 4; q++) d[mb][nb][q] = 0.f;

        const uint32_t aB = sbase + SM_A + buf * A_STRIDE;
        const uint32_t bB = sbase + SM_B;
#pragma unroll
        for (int kk = 0; kk < 8; kk++) {
            const int kblk0 = kk * 2;
            uint32_t a[2][4];
#pragma unroll
            for (int mb = 0; mb < 2; mb++) {
                uint32_t addr = aB + aswz(mbase + mb * 16 + aRow, kblk0 + aKs);
                ldsm_x4(a[mb][0], a[mb][1], a[mb][2], a[mb][3], addr);
            }
#pragma unroll
            for (int nb2 = 0; nb2 < 2; nb2++) {
                uint32_t addr = bB + aswz(nbase + nb2 * 16 + bRow,
                                          kblk0 + (bTile & 1));
                uint32_t b0, b1, b2, b3;
                ldsm_x4(b0, b1, b2, b3, addr);
                uint32_t blo[2] = {b0, b1};
                uint32_t bhi[2] = {b2, b3};
                mma16816(d[0][nb2 * 2 + 0], a[0], blo);
                mma16816(d[1][nb2 * 2 + 0], a[1], blo);
                mma16816(d[0][nb2 * 2 + 1], a[0], bhi);
                mma16816(d[1][nb2 * 2 + 1], a[1], bhi);
            }
        }

        // ---- epilogue: +bias, cols<128 -> agg(h0) fp16, else h1 fp16 ----
#pragma unroll
        for (int mb = 0; mb < 2; mb++) {
#pragma unroll
            for (int h = 0; h < 2; h++) {
                int row = tb + mbase + mb * 16 + (lane >> 2) + h * 8;
                if (row >= n) continue;
#pragma unroll
                for (int nb = 0; nb < 4; nb++) {
                    int col = nbase + nb * 8 + colq;
                    float2 bv = __ldg((const float2*)(bias256 + col));
                    float vx = d[mb][nb][2 * h + 0] + bv.x;
                    float vy = d[mb][nb][2 * h + 1] + bv.y;
                    uint32_t pv = pkh(vx, vy);
                    if (col < 128)
                        *(uint32_t*)(agg + (size_t)row * 128 + col) = pv;
                    else
                        *(uint32_t*)(h1v + (size_t)row * 128 + (col - 128)) = pv;
                }
            }
        }

        if (!hasNext) break;

        // ---- convert + store prefetched tile into other buffer ----
        {
            char* ab = sm + SM_A + (buf ^ 1) * A_STRIDE;
#pragma unroll
            for (int u = 0; u < 8; u++) {
                int idx = u * 512 + tid;
                int row = idx >> 6, p = idx & 63;
                float2 xv = pf[u];
                if (MODE == 1) { xv.x = fmaxf(xv.x, 0.f); xv.y = fmaxf(xv.y, 0.f); }
                uint32_t off = aswz(row, p >> 2) + (p & 3) * 4;
                *(uint32_t*)(ab + off) = pkh(xv.x, xv.y);
            }
        }
        tile = next;
        __syncthreads();
    }
}

// ======================= CSR gather (128-wide, fp16, shuffle-adj) ==========
// Warp per node. Adjacency for up to 32 neighbors loaded with ONE coalesced
// LDG (lane l reads adj[rs+l]) and broadcast via shuffle, so all neighbor-row
// loads are independent (no adj->row pointer chase).
__global__ __launch_bounds__(256)
void gather128_kernel(const int* __restrict__ rowstart, const int* __restrict__ adj,
                      const __half* __restrict__ h1, __half* __restrict__ agg, int n)
{
    int node = blockIdx.x * 8 + (threadIdx.x >> 5);
    int lane = threadIdx.x & 31;
    if (node >= n) return;
    int rs = __ldg(&rowstart[node]);
    int re = __ldg(&rowstart[node + 1]);
    int k0 = lane * 4;
    uint2* ap = (uint2*)(agg + (size_t)node * 128 + k0);
    float4 acc = h4tof4(*ap);

    for (int base = rs; base < re; base += 32) {
        int cnt = re - base;
        if (cnt > 32) cnt = 32;
        int aj = (lane < cnt) ? __ldg(&adj[base + lane]) : 0;
        int t = 0;
        for (; t + 3 < cnt; t += 4) {
            int j0 = __shfl_sync(0xffffffffu, aj, t);
            int j1 = __shfl_sync(0xffffffffu, aj, t + 1);
            int j2 = __shfl_sync(0xffffffffu, aj, t + 2);
            int j3 = __shfl_sync(0xffffffffu, aj, t + 3);
            float4 v0 = h4tof4(__ldg((const uint2*)(h1 + (size_t)j0 * 128 + k0)));
            float4 v1 = h4tof4(__ldg((const uint2*)(h1 + (size_t)j1 * 128 + k0)));
            float4 v2 = h4tof4(__ldg((const uint2*)(h1 + (size_t)j2 * 128 + k0)));
            float4 v3 = h4tof4(__ldg((const uint2*)(h1 + (size_t)j3 * 128 + k0)));
            acc.x += v0.x + v1.x + v2.x + v3.x;
            acc.y += v0.y + v1.y + v2.y + v3.y;
            acc.z += v0.z + v1.z + v2.z + v3.z;
            acc.w += v0.w + v1.w + v2.w + v3.w;
        }
        if (t + 1 < cnt) {
            int j0 = __shfl_sync(0xffffffffu, aj, t);
            int j1 = __shfl_sync(0xffffffffu, aj, t + 1);
            float4 v0 = h4tof4(__ldg((const uint2*)(h1 + (size_t)j0 * 128 + k0)));
            float4 v1 = h4tof4(__ldg((const uint2*)(h1 + (size_t)j1 * 128 + k0)));
            acc.x += v0.x + v1.x; acc.y += v0.y + v1.y;
            acc.z += v0.z + v1.z; acc.w += v0.w + v1.w;
            t += 2;
        }
        if (t < cnt) {
            int j = __shfl_sync(0xffffffffu, aj, t);
            float4 v = h4tof4(__ldg((const uint2*)(h1 + (size_t)j * 128 + k0)));
            acc.x += v.x; acc.y += v.y; acc.z += v.z; acc.w += v.w;
        }
    }
    *ap = f4toh4(acc);
}

// ======================= final layer (dout=3), fp16 input ===================
__global__ __launch_bounds__(256)
void final_kernel(const __half* __restrict__ in, const float* __restrict__ feat,
                  const float* __restrict__ W0, const float* __restrict__ b0,
                  const float* __restrict__ W1, const float* __restrict__ b1,
                  float* __restrict__ out, float* __restrict__ h1s, int n)
{
    __shared__ float ws[128][6];
    __shared__ float bs[6];
    int tid = threadIdx.x;
    for (int idx = tid; idx < 768; idx += 256) {
        int k = idx / 6, j = idx % 6;
        ws[k][j] = (j < 3) ? __ldg(&W0[k * 3 + j]) : __ldg(&W1[k * 3 + (j - 3)]);
    }
    if (tid < 3)      bs[tid] = __ldg(&b0[tid]);
    else if (tid < 6) bs[tid] = __ldg(&b1[tid - 3]);
    __syncthreads();

    int lane = tid & 31;
    int node = blockIdx.x * 8 + (tid >> 5);
    if (node >= n) return;

    float acc[6] = {0.f, 0.f, 0.f, 0.f, 0.f, 0.f};
    const __half* xin = in + (size_t)node * 128;
    const float*  xf  = feat + (size_t)node * 128;
#pragma unroll
    for (int f = 0; f < 4; f++) {
        int k = f * 32 + lane;
        float x = fmaxf(__half2float(xin[k]), 0.f) + xf[k];
#pragma unroll
        for (int j = 0; j < 6; j++) acc[j] += x * ws[k][j];
    }
#pragma unroll
    for (int j = 0; j < 6; j++) {
#pragma unroll
        for (int o = 16; o > 0; o >>= 1)
            acc[j] += __shfl_xor_sync(0xffffffffu, acc[j], o);
    }
    if (lane == 0) {
        out[node * 3 + 0] = acc[0] + bs[0];
        out[node * 3 + 1] = acc[1] + bs[1];
        out[node * 3 + 2] = acc[2] + bs[2];
        h1s[node * 3 + 0] = acc[3] + bs[3];
        h1s[node * 3 + 1] = acc[4] + bs[4];
        h1s[node * 3 + 2] = acc[5] + bs[5];
    }
}

__global__ void gather3_kernel(const int* __restrict__ rowstart,
                               const int* __restrict__ adj,
                               const float* __restrict__ h1s,
                               float* __restrict__ out, int n)
{
    int i = blockIdx.x * blockDim.x + threadIdx.x;
    if (i >= n) return;
    int rs = __ldg(&rowstart[i]);
    int re = __ldg(&rowstart[i + 1]);
    float a0 = 0.f, a1 = 0.f, a2 = 0.f;
    for (int e = rs; e < re; e++) {
        int j = __ldg(&adj[e]);
        a0 += __ldg(&h1s[j * 3 + 0]);
        a1 += __ldg(&h1s[j * 3 + 1]);
        a2 += __ldg(&h1s[j * 3 + 2]);
    }
    out[i * 3 + 0] += a0;
    out[i * 3 + 1] += a1;
    out[i * 3 + 2] += a2;
}

// ======================= launch ============================================
extern "C" void kernel_launch(void* const* d_in, const int* in_sizes, int n_in,
                              void* d_out, int out_size)
{
    const float* feat  = (const float*)d_in[0];
    const int2*  edges = (const int2*) d_in[1];
    const int N = in_sizes[0] / 128;
    const int E = in_sizes[1] / 2;

    const float *W0[4], *B0[4], *W1[4], *B1[4];
    for (int i = 0; i < 4; i++) {
        W0[i] = (const float*)d_in[2 + 4 * i];
        B0[i] = (const float*)d_in[3 + 4 * i];
        W1[i] = (const float*)d_in[4 + 4 * i];
        B1[i] = (const float*)d_in[5 + 4 * i];
    }

    __half *bufA, *bufB, *h1, *w16All;
    float *h1s, *biasAll;
    int *deg, *cur, *rowstart, *adj, *bsum;
    cudaGetSymbolAddress((void**)&bufA, g_bufA);
    cudaGetSymbolAddress((void**)&bufB, g_bufB);
    cudaGetSymbolAddress((void**)&h1,   g_h1);
    cudaGetSymbolAddress((void**)&h1s,  g_h1s);
    cudaGetSymbolAddress((void**)&w16All, g_W16);
    cudaGetSymbolAddress((void**)&biasAll, g_bias);
    cudaGetSymbolAddress((void**)&deg, g_deg);
    cudaGetSymbolAddress((void**)&cur, g_cur);
    cudaGetSymbolAddress((void**)&rowstart, g_rowstart);
    cudaGetSymbolAddress((void**)&adj, g_adj);
    cudaGetSymbolAddress((void**)&bsum, g_bsum);

    cudaFuncSetAttribute((const void*)gemm_persist_kernel<0, false>,
                         cudaFuncAttributeMaxDynamicSharedMemorySize, SM_DYN);
    cudaFuncSetAttribute((const void*)gemm_persist_kernel<1, true>,
                         cudaFuncAttributeMaxDynamicSharedMemorySize, SM_DYN);

    // weight prep
    for (int l = 0; l < 3; l++) {
        prep_w_kernel<<<16, 256>>>(W0[l], B0[l], W1[l], B1[l],
                                   w16All + l * 256 * 128, biasAll + l * 256);
    }

    // CSR build
    const int NB = (N + 1023) / 1024;
    zero_deg_kernel<<<(N + 255) / 256, 256>>>(deg, N);
    count_deg_kernel<<<(E + 255) / 256, 256>>>(edges, deg, E);
    scanA_kernel<<<NB, 1024>>>(deg, rowstart, bsum, N);
    scanB_kernel<<<1, 512>>>(bsum, NB);
    scanC_kernel<<<NB, 1024>>>(rowstart, cur, bsum, N, 2 * E);
    fill_adj_kernel<<<(E + 255) / 256, 256>>>(edges, cur, adj, E);

    const int numTiles = (N + 63) / 64;
    const int PGRID = 148;
    const int gaBlocks = (N + 7) / 8;
    float* out = (float*)d_out;

    gemm_persist_kernel<0, false><<<PGRID, 512, SM_DYN>>>(feat, w16All, biasAll,
                                                          bufA, h1, N, numTiles);
    gather128_kernel<<<gaBlocks, 256>>>(rowstart, adj, h1, bufA, N);

    gemm_persist_kernel<1, true><<<PGRID, 512, SM_DYN>>>(bufA, w16All + 256 * 128,
                                                         biasAll + 256, bufB, h1, N, numTiles);
    gather128_kernel<<<gaBlocks, 256>>>(rowstart, adj, h1, bufB, N);

    gemm_persist_kernel<1, true><<<PGRID, 512, SM_DYN>>>(bufB, w16All + 2 * 256 * 128,
                                                         biasAll + 2 * 256, bufA, h1, N, numTiles);
    gather128_kernel<<<gaBlocks, 256>>>(rowstart, adj, h1, bufA, N);

    final_kernel<<<gaBlocks, 256>>>(bufA, feat, W0[3], B0[3], W1[3], B1[3], out, h1s, N);
    gather3_kernel<<<(N + 255) / 256, 256>>>(rowstart, adj, h1s, out, N);
}